// round 1
// baseline (speedup 1.0000x reference)
#include <cuda_runtime.h>
#include <math.h>

#define B_ 4
#define S_ 2048
#define D_ 2048
#define NH_ 16
#define NKV_ 4
#define HD_ 128
#define GROUPS_ 4
#define MTOK (B_*S_)      /* 8192 */
#define KVD (NKV_*HD_)    /* 512  */

// Scratch (device globals: allocation-free per harness rules)
__device__ float g_q[(size_t)MTOK * D_];
__device__ float g_k[(size_t)MTOK * KVD];
__device__ float g_v[(size_t)MTOK * KVD];
__device__ float g_ctx[(size_t)MTOK * D_];

// ---------------------------------------------------------------------------
// GEMM: C[M,N] = A[M,K] @ Bw[N,K]^T (+ bias[N]), all row-major, fp32.
// 128x64 block tile, BK=8, 256 threads, 8x4 per-thread tile,
// single-smem-buffer + register prefetch double buffering.
// ---------------------------------------------------------------------------
#define GBM 128
#define GBN 64
#define GBK 8
#define AS_STR (GBM + 4)   /* 132: conflict-free transposed stores */
#define BS_STR (GBN + 4)   /* 68 */

__global__ __launch_bounds__(256) void gemm_bias_nt(
    const float* __restrict__ A, const float* __restrict__ Bw,
    const float* __restrict__ bias, float* __restrict__ C,
    int M, int N, int K)
{
    __shared__ float As[GBK][AS_STR];
    __shared__ float Bs[GBK][BS_STR];

    const int tid = threadIdx.x;
    const int bm = blockIdx.y * GBM;
    const int bn = blockIdx.x * GBN;

    const int arow = tid >> 1;           // 0..127
    const int acol = (tid & 1) * 4;      // 0 or 4
    const int ty = tid >> 4;             // 0..15 (row group, 8 rows each)
    const int tx = tid & 15;             // 0..15 (col group, 4 cols each)

    float acc[8][4];
    #pragma unroll
    for (int i = 0; i < 8; i++)
        #pragma unroll
        for (int j = 0; j < 4; j++) acc[i][j] = 0.0f;

    // preload tile 0
    {
        float4 av = *(const float4*)&A[(size_t)(bm + arow) * K + acol];
        As[acol+0][arow] = av.x; As[acol+1][arow] = av.y;
        As[acol+2][arow] = av.z; As[acol+3][arow] = av.w;
        if (tid < 128) {
            float4 bv = *(const float4*)&Bw[(size_t)(bn + arow) * K + acol];
            Bs[acol+0][arow] = bv.x; Bs[acol+1][arow] = bv.y;
            Bs[acol+2][arow] = bv.z; Bs[acol+3][arow] = bv.w;
        }
    }

    for (int k0 = 0; k0 < K; k0 += GBK) {
        __syncthreads();   // current tile visible
        const bool more = (k0 + GBK) < K;
        float4 aN, bN;
        if (more) {
            aN = *(const float4*)&A[(size_t)(bm + arow) * K + k0 + GBK + acol];
            if (tid < 128)
                bN = *(const float4*)&Bw[(size_t)(bn + arow) * K + k0 + GBK + acol];
        }

        #pragma unroll
        for (int kk = 0; kk < GBK; kk++) {
            float4 a0 = *(const float4*)&As[kk][ty * 8];
            float4 a1 = *(const float4*)&As[kk][ty * 8 + 4];
            float4 b0 = *(const float4*)&Bs[kk][tx * 4];
            float ar[8] = {a0.x, a0.y, a0.z, a0.w, a1.x, a1.y, a1.z, a1.w};
            float br[4] = {b0.x, b0.y, b0.z, b0.w};
            #pragma unroll
            for (int i = 0; i < 8; i++)
                #pragma unroll
                for (int j = 0; j < 4; j++)
                    acc[i][j] += ar[i] * br[j];
        }
        __syncthreads();   // all reads done before overwrite
        if (more) {
            As[acol+0][arow] = aN.x; As[acol+1][arow] = aN.y;
            As[acol+2][arow] = aN.z; As[acol+3][arow] = aN.w;
            if (tid < 128) {
                Bs[acol+0][arow] = bN.x; Bs[acol+1][arow] = bN.y;
                Bs[acol+2][arow] = bN.z; Bs[acol+3][arow] = bN.w;
            }
        }
    }

    #pragma unroll
    for (int i = 0; i < 8; i++) {
        const int row = bm + ty * 8 + i;
        const int col = bn + tx * 4;
        float bb = bias ? 0.0f : 0.0f;
        float b0 = bias ? bias[col + 0] : 0.0f;
        float b1 = bias ? bias[col + 1] : 0.0f;
        float b2 = bias ? bias[col + 2] : 0.0f;
        float b3 = bias ? bias[col + 3] : 0.0f;
        (void)bb;
        float4 outv = make_float4(acc[i][0] + b0, acc[i][1] + b1,
                                  acc[i][2] + b2, acc[i][3] + b3);
        *(float4*)&C[(size_t)row * N + col] = outv;
    }
}

// ---------------------------------------------------------------------------
// RoPE in place on t: [B*S, nheads, 128]. One thread per (token, head, j<64).
// ---------------------------------------------------------------------------
__global__ void rope_kernel(float* __restrict__ t, int nheads)
{
    const int idx = blockIdx.x * blockDim.x + threadIdx.x;
    const int j = idx & 63;
    const int rest = idx >> 6;
    const int head = rest % nheads;
    const int tok = rest / nheads;      // 0..B*S-1
    const int s = tok & (S_ - 1);       // position

    const float expo = (float)(2 * j) / 128.0f;
    const float inv = 1.0f / powf(1.0e6f, expo);
    const float ang = (float)s * inv;
    float sn, cs;
    sincosf(ang, &sn, &cs);

    const size_t base = ((size_t)tok * nheads + head) * HD_;
    const float x1 = t[base + j];
    const float x2 = t[base + j + 64];
    t[base + j]      = x1 * cs - x2 * sn;
    t[base + j + 64] = x2 * cs + x1 * sn;
}

// ---------------------------------------------------------------------------
// Flash attention, fp32, causal, GQA. 64 q-rows x 64 kv-cols tiles, 256 thr.
// smem: Qs/Ks/Vs [64][132], Ps [64][68], m/l/alpha [64] -> 119,552 B dynamic.
// ---------------------------------------------------------------------------
#define FBM 64
#define FBN 64
#define TSTR 132
#define PSTR 68

__global__ __launch_bounds__(256) void flash_attn()
{
    extern __shared__ float sm[];
    float* Qs   = sm;                    // [64][132]
    float* Ks   = Qs + 64 * TSTR;
    float* Vs   = Ks + 64 * TSTR;
    float* Ps   = Vs + 64 * TSTR;        // [64][68]
    float* mrow = Ps + 64 * PSTR;
    float* lrow = mrow + 64;
    float* arow = lrow + 64;

    const int qt = blockIdx.x;           // 0..31
    const int h  = blockIdx.y;
    const int b  = blockIdx.z;
    const int kvh = h / GROUPS_;
    const int tid = threadIdx.x;
    const int qbase = qt * FBM;

    // load Q tile: [tok][hd], coalesced float4, conflict-free stores
    const float* qptr = g_q + (((size_t)b * S_ + qbase) * NH_ + h) * HD_;
    #pragma unroll
    for (int it = 0; it < 8; it++) {
        int idx = tid + it * 256;
        int tok = idx >> 5;
        int hd  = (idx & 31) << 2;
        *(float4*)(Qs + tok * TSTR + hd) =
            *(const float4*)(qptr + (size_t)tok * NH_ * HD_ + hd);
    }
    if (tid < 64) { mrow[tid] = -1e30f; lrow[tid] = 0.0f; }

    const int ty = tid >> 4;             // 0..15
    const int tx = tid & 15;             // 0..15
    const int r0 = ty * 4;               // 4 rows per thread (scores & O)

    float oacc[4][8];
    #pragma unroll
    for (int i = 0; i < 4; i++)
        #pragma unroll
        for (int j = 0; j < 8; j++) oacc[i][j] = 0.0f;

    const float scale = 0.08838834764831845f;  // 1/sqrt(128)

    const float* kbp = g_k + ((size_t)b * S_ * NKV_ + kvh) * HD_;
    const float* vbp = g_v + ((size_t)b * S_ * NKV_ + kvh) * HD_;

    for (int jt = 0; jt <= qt; jt++) {
        __syncthreads();   // previous tile's Ps/Ks/Vs reads complete
        const float* kp = kbp + (size_t)(jt * FBN) * NKV_ * HD_;
        const float* vp = vbp + (size_t)(jt * FBN) * NKV_ * HD_;
        #pragma unroll
        for (int it = 0; it < 8; it++) {
            int idx = tid + it * 256;
            int tok = idx >> 5;
            int hd  = (idx & 31) << 2;
            *(float4*)(Ks + tok * TSTR + hd) =
                *(const float4*)(kp + (size_t)tok * NKV_ * HD_ + hd);
            *(float4*)(Vs + tok * TSTR + hd) =
                *(const float4*)(vp + (size_t)tok * NKV_ * HD_ + hd);
        }
        __syncthreads();

        // ---- scores: S = Q @ K^T ; thread cols are tx + 16*j (conflict-free)
        float sacc[4][4];
        #pragma unroll
        for (int i = 0; i < 4; i++)
            #pragma unroll
            for (int j = 0; j < 4; j++) sacc[i][j] = 0.0f;

        #pragma unroll 4
        for (int kk = 0; kk < HD_; kk += 4) {
            float4 qr[4], kr[4];
            #pragma unroll
            for (int i = 0; i < 4; i++)
                qr[i] = *(const float4*)(Qs + (r0 + i) * TSTR + kk);
            #pragma unroll
            for (int j = 0; j < 4; j++)
                kr[j] = *(const float4*)(Ks + (tx + 16 * j) * TSTR + kk);
            #pragma unroll
            for (int i = 0; i < 4; i++)
                #pragma unroll
                for (int j = 0; j < 4; j++)
                    sacc[i][j] += qr[i].x * kr[j].x + qr[i].y * kr[j].y +
                                  qr[i].z * kr[j].z + qr[i].w * kr[j].w;
        }

        const bool diag = (jt == qt);
        #pragma unroll
        for (int i = 0; i < 4; i++) {
            const int rr = r0 + i;
            #pragma unroll
            for (int j = 0; j < 4; j++) {
                const int cc = tx + 16 * j;
                float sv = sacc[i][j] * scale;
                if (diag && cc > rr) sv = -1e30f;
                Ps[rr * PSTR + cc] = sv;
            }
        }
        __syncthreads();

        // ---- online softmax: 4 threads per row
        {
            const int row = tid >> 2;
            const int part = tid & 3;
            const int c0 = part * 16;
            float mx = -1e30f;
            #pragma unroll
            for (int c = 0; c < 16; c++)
                mx = fmaxf(mx, Ps[row * PSTR + c0 + c]);
            mx = fmaxf(mx, __shfl_xor_sync(0xffffffffu, mx, 1));
            mx = fmaxf(mx, __shfl_xor_sync(0xffffffffu, mx, 2));
            const float m_old = mrow[row];
            const float m_new = fmaxf(m_old, mx);
            float ssum = 0.0f;
            #pragma unroll
            for (int c = 0; c < 16; c++) {
                float p = __expf(Ps[row * PSTR + c0 + c] - m_new);
                Ps[row * PSTR + c0 + c] = p;
                ssum += p;
            }
            ssum += __shfl_xor_sync(0xffffffffu, ssum, 1);
            ssum += __shfl_xor_sync(0xffffffffu, ssum, 2);
            if (part == 0) {
                const float al = __expf(m_old - m_new);
                arow[row] = al;
                lrow[row] = lrow[row] * al + ssum;
                mrow[row] = m_new;
            }
        }
        __syncthreads();

        // ---- O = O*alpha + P @ V ; thread cols: 4*tx..+3 and 64+4*tx..+3
        float al[4];
        #pragma unroll
        for (int i = 0; i < 4; i++) al[i] = arow[r0 + i];
        #pragma unroll
        for (int i = 0; i < 4; i++)
            #pragma unroll
            for (int j = 0; j < 8; j++) oacc[i][j] *= al[i];

        #pragma unroll 4
        for (int kk = 0; kk < FBN; kk++) {
            float pv[4];
            #pragma unroll
            for (int i = 0; i < 4; i++) pv[i] = Ps[(r0 + i) * PSTR + kk];
            float4 v0 = *(const float4*)(Vs + kk * TSTR + 4 * tx);
            float4 v1 = *(const float4*)(Vs + kk * TSTR + 64 + 4 * tx);
            #pragma unroll
            for (int i = 0; i < 4; i++) {
                oacc[i][0] += pv[i] * v0.x;  oacc[i][1] += pv[i] * v0.y;
                oacc[i][2] += pv[i] * v0.z;  oacc[i][3] += pv[i] * v0.w;
                oacc[i][4] += pv[i] * v1.x;  oacc[i][5] += pv[i] * v1.y;
                oacc[i][6] += pv[i] * v1.z;  oacc[i][7] += pv[i] * v1.w;
            }
        }
    }

    // ---- epilogue: normalize + write ctx in [b, s, h, hd] layout
    float* optr = g_ctx + (((size_t)b * S_ + qbase) * NH_ + h) * HD_;
    #pragma unroll
    for (int i = 0; i < 4; i++) {
        const float linv = 1.0f / lrow[r0 + i];
        const size_t off = (size_t)(r0 + i) * NH_ * HD_;
        float4 w0 = make_float4(oacc[i][0]*linv, oacc[i][1]*linv,
                                oacc[i][2]*linv, oacc[i][3]*linv);
        float4 w1 = make_float4(oacc[i][4]*linv, oacc[i][5]*linv,
                                oacc[i][6]*linv, oacc[i][7]*linv);
        *(float4*)(optr + off + 4 * tx) = w0;
        *(float4*)(optr + off + 64 + 4 * tx) = w1;
    }
}

// ---------------------------------------------------------------------------
extern "C" void kernel_launch(void* const* d_in, const int* in_sizes, int n_in,
                              void* d_out, int out_size)
{
    (void)in_sizes; (void)n_in; (void)out_size;
    const float* x    = (const float*)d_in[0];
    const float* wq_w = (const float*)d_in[1];
    const float* wq_b = (const float*)d_in[2];
    const float* wk_w = (const float*)d_in[3];
    const float* wk_b = (const float*)d_in[4];
    const float* wv_w = (const float*)d_in[5];
    const float* wv_b = (const float*)d_in[6];
    const float* wo_w = (const float*)d_in[7];
    float* out = (float*)d_out;

    float *pq, *pk, *pv, *pctx;
    cudaGetSymbolAddress((void**)&pq,   g_q);
    cudaGetSymbolAddress((void**)&pk,   g_k);
    cudaGetSymbolAddress((void**)&pv,   g_v);
    cudaGetSymbolAddress((void**)&pctx, g_ctx);

    const size_t FL_SMEM = (size_t)(3 * 64 * TSTR + 64 * PSTR + 3 * 64) * sizeof(float);
    cudaFuncSetAttribute(flash_attn, cudaFuncAttributeMaxDynamicSharedMemorySize,
                         (int)FL_SMEM);

    // QKV projections
    gemm_bias_nt<<<dim3(D_  / GBN, MTOK / GBM), 256>>>(x, wq_w, wq_b, pq,  MTOK, D_,  D_);
    gemm_bias_nt<<<dim3(KVD / GBN, MTOK / GBM), 256>>>(x, wk_w, wk_b, pk,  MTOK, KVD, D_);
    gemm_bias_nt<<<dim3(KVD / GBN, MTOK / GBM), 256>>>(x, wv_w, wv_b, pv,  MTOK, KVD, D_);

    // RoPE on q and k
    rope_kernel<<<(MTOK * NH_  * 64) / 256, 256>>>(pq, NH_);
    rope_kernel<<<(MTOK * NKV_ * 64) / 256, 256>>>(pk, NKV_);

    // causal GQA flash attention -> g_ctx
    flash_attn<<<dim3(S_ / FBM, NH_, B_), 256, FL_SMEM>>>();

    // output projection (no bias)
    gemm_bias_nt<<<dim3(D_ / GBN, MTOK / GBM), 256>>>(pctx, wo_w, nullptr, out, MTOK, D_, D_);
}

// round 3
// speedup vs baseline: 1.6491x; 1.6491x over previous
#include <cuda_runtime.h>
#include <cuda_bf16.h>
#include <math.h>
#include <cstdint>

#define B_ 4
#define S_ 2048
#define D_ 2048
#define NH_ 16
#define NKV_ 4
#define HD_ 128
#define GROUPS_ 4
#define MTOK (B_*S_)      /* 8192 */
#define KVD (NKV_*HD_)    /* 512  */

// fp32 scratch
__device__ float g_q[(size_t)MTOK * D_];
__device__ float g_k[(size_t)MTOK * KVD];
__device__ float g_v[(size_t)MTOK * KVD];
__device__ float g_ctx[(size_t)MTOK * D_];

// bf16 hi/lo split buffers
__device__ __nv_bfloat16 g_xh[(size_t)MTOK * D_];
__device__ __nv_bfloat16 g_xl[(size_t)MTOK * D_];
__device__ __nv_bfloat16 g_wqh[(size_t)D_ * D_];
__device__ __nv_bfloat16 g_wql[(size_t)D_ * D_];
__device__ __nv_bfloat16 g_wkh[(size_t)KVD * D_];
__device__ __nv_bfloat16 g_wkl[(size_t)KVD * D_];
__device__ __nv_bfloat16 g_wvh[(size_t)KVD * D_];
__device__ __nv_bfloat16 g_wvl[(size_t)KVD * D_];
__device__ __nv_bfloat16 g_woh[(size_t)D_ * D_];
__device__ __nv_bfloat16 g_wol[(size_t)D_ * D_];
__device__ __nv_bfloat16 g_ch[(size_t)MTOK * D_];
__device__ __nv_bfloat16 g_cl[(size_t)MTOK * D_];

// ============================================================================
// helpers (portable PTX only: mma.sync sm_80, cp.async sm_80)
// ============================================================================
__device__ __forceinline__ uint32_t smem_u32(const void* p) {
    uint32_t a;
    asm("{ .reg .u64 t; cvta.to.shared.u64 t, %1; cvt.u32.u64 %0, t; }"
        : "=r"(a) : "l"(p));
    return a;
}
__device__ __forceinline__ uint32_t lds32(uint32_t a) {
    uint32_t v;
    asm volatile("ld.shared.b32 %0, [%1];" : "=r"(v) : "r"(a));
    return v;
}
__device__ __forceinline__ void cp16(uint32_t dst, const void* src) {
    asm volatile("cp.async.cg.shared.global [%0], [%1], 16;"
                 :: "r"(dst), "l"(src) : "memory");
}
__device__ __forceinline__ void mma_bf16(float* c,
    uint32_t a0, uint32_t a1, uint32_t a2, uint32_t a3,
    uint32_t b0, uint32_t b1)
{
    asm volatile(
        "mma.sync.aligned.m16n8k16.row.col.f32.bf16.bf16.f32 "
        "{%0,%1,%2,%3}, {%4,%5,%6,%7}, {%8,%9}, {%0,%1,%2,%3};"
        : "+f"(c[0]), "+f"(c[1]), "+f"(c[2]), "+f"(c[3])
        : "r"(a0), "r"(a1), "r"(a2), "r"(a3), "r"(b0), "r"(b1));
}

// ============================================================================
// split: fp32 -> hi bf16 + lo bf16 (x = hi + lo to ~2^-18 rel)
// ============================================================================
__global__ void split_bf16(const float* __restrict__ in,
                           __nv_bfloat16* __restrict__ hi,
                           __nv_bfloat16* __restrict__ lo, int n)
{
    const int i = (blockIdx.x * blockDim.x + threadIdx.x) * 4;
    if (i >= n) return;
    float4 v = *(const float4*)(in + i);
    __nv_bfloat16 h0 = __float2bfloat16(v.x);
    __nv_bfloat16 h1 = __float2bfloat16(v.y);
    __nv_bfloat16 h2 = __float2bfloat16(v.z);
    __nv_bfloat16 h3 = __float2bfloat16(v.w);
    __nv_bfloat16 l0 = __float2bfloat16(v.x - __bfloat162float(h0));
    __nv_bfloat16 l1 = __float2bfloat16(v.y - __bfloat162float(h1));
    __nv_bfloat16 l2 = __float2bfloat16(v.z - __bfloat162float(h2));
    __nv_bfloat16 l3 = __float2bfloat16(v.w - __bfloat162float(h3));
    __nv_bfloat162* H = (__nv_bfloat162*)(hi + i);
    __nv_bfloat162* L = (__nv_bfloat162*)(lo + i);
    H[0] = __halves2bfloat162(h0, h1);
    H[1] = __halves2bfloat162(h2, h3);
    L[0] = __halves2bfloat162(l0, l1);
    L[1] = __halves2bfloat162(l2, l3);
}

// ============================================================================
// bf16x3 GEMM: C[M,N] = A[M,K] @ Bw[N,K]^T (+ bias), fp32 out.
// A,B given as hi/lo bf16. CTA 128x128, K-chunk 32, 8 warps x (64x32),
// mma.sync m16n8k16, cp.async double-buffered smem.
// ============================================================================
#define RSTR 80                  /* smem row stride bytes (conflict-free) */
#define MATB (128 * RSTR)        /* 10240 B per matrix tile */
#define STG  (4 * MATB)          /* stage: Ah Al Bh Bl = 40960 B */
#define SMEM_GEMM (2 * STG)      /* 81920 B */

__global__ __launch_bounds__(256) void gemm_bf16x3(
    const __nv_bfloat16* __restrict__ Ah, const __nv_bfloat16* __restrict__ Al,
    const __nv_bfloat16* __restrict__ Bh, const __nv_bfloat16* __restrict__ Bl,
    const float* __restrict__ bias, float* __restrict__ C,
    int M, int N, int K)
{
    extern __shared__ char smc[];
    const uint32_t sb = smem_u32(smc);
    const int tid = threadIdx.x;
    const int wid = tid >> 5, lane = tid & 31;
    const int bm = blockIdx.y * 128, bn = blockIdx.x * 128;
    const int wm = wid & 1, wn = wid >> 1;          // 2x4 warp grid
    const int g = lane >> 2, tg = lane & 3;

    float acc[4][4][4];
    #pragma unroll
    for (int i = 0; i < 4; i++)
        #pragma unroll
        for (int j = 0; j < 4; j++)
            #pragma unroll
            for (int r = 0; r < 4; r++) acc[i][j][r] = 0.0f;

    const int T = K / 32;

    // issue one stage's cp.asyncs (A/B tiles 128x32 bf16, hi+lo)
    auto issue = [&](int s, int k0) {
        const uint32_t sbase = sb + s * STG;
        #pragma unroll
        for (int i = 0; i < 2; i++) {
            const int idx = tid + i * 256;
            const int row = idx >> 2, c8 = idx & 3;
            const size_t goA = (size_t)(bm + row) * K + k0 + c8 * 8;
            const size_t goB = (size_t)(bn + row) * K + k0 + c8 * 8;
            const uint32_t so = (uint32_t)(row * RSTR + c8 * 16);
            cp16(sbase + so,            Ah + goA);
            cp16(sbase + MATB + so,     Al + goA);
            cp16(sbase + 2 * MATB + so, Bh + goB);
            cp16(sbase + 3 * MATB + so, Bl + goB);
        }
        asm volatile("cp.async.commit_group;" ::: "memory");
    };

    issue(0, 0);

    for (int t = 0; t < T; t++) {
        if (t + 1 < T) {
            issue((t + 1) & 1, (t + 1) * 32);
            asm volatile("cp.async.wait_group 1;" ::: "memory");
        } else {
            asm volatile("cp.async.wait_group 0;" ::: "memory");
        }
        __syncthreads();

        const uint32_t stb = sb + (t & 1) * STG;
        const uint32_t aB = stb + (uint32_t)((wm * 64 + g) * RSTR + tg * 4);
        const uint32_t bB = stb + 2 * MATB + (uint32_t)((wn * 32 + g) * RSTR + tg * 4);

        #pragma unroll
        for (int ks = 0; ks < 2; ks++) {
            const uint32_t ko = ks * 32;
            uint32_t bh[4][2], bl[4][2];
            #pragma unroll
            for (int nt = 0; nt < 4; nt++) {
                const uint32_t a = bB + nt * 8 * RSTR + ko;
                bh[nt][0] = lds32(a);
                bh[nt][1] = lds32(a + 16);
                bl[nt][0] = lds32(a + MATB);
                bl[nt][1] = lds32(a + MATB + 16);
            }
            #pragma unroll
            for (int mt = 0; mt < 4; mt++) {
                const uint32_t a = aB + mt * 16 * RSTR + ko;
                const uint32_t ah0 = lds32(a);
                const uint32_t ah1 = lds32(a + 8 * RSTR);
                const uint32_t ah2 = lds32(a + 16);
                const uint32_t ah3 = lds32(a + 8 * RSTR + 16);
                const uint32_t al0 = lds32(a + MATB);
                const uint32_t al1 = lds32(a + MATB + 8 * RSTR);
                const uint32_t al2 = lds32(a + MATB + 16);
                const uint32_t al3 = lds32(a + MATB + 8 * RSTR + 16);
                #pragma unroll
                for (int nt = 0; nt < 4; nt++) {
                    mma_bf16(acc[mt][nt], ah0, ah1, ah2, ah3, bh[nt][0], bh[nt][1]);
                    mma_bf16(acc[mt][nt], ah0, ah1, ah2, ah3, bl[nt][0], bl[nt][1]);
                    mma_bf16(acc[mt][nt], al0, al1, al2, al3, bh[nt][0], bh[nt][1]);
                }
            }
        }
        __syncthreads();
    }

    // epilogue
    #pragma unroll
    for (int mt = 0; mt < 4; mt++) {
        const int r0 = bm + wm * 64 + mt * 16 + g;
        #pragma unroll
        for (int nt = 0; nt < 4; nt++) {
            const int col = bn + wn * 32 + nt * 8 + tg * 2;
            float b0 = 0.f, b1 = 0.f;
            if (bias) { b0 = bias[col]; b1 = bias[col + 1]; }
            float2 w0 = make_float2(acc[mt][nt][0] + b0, acc[mt][nt][1] + b1);
            float2 w1 = make_float2(acc[mt][nt][2] + b0, acc[mt][nt][3] + b1);
            *(float2*)&C[(size_t)r0 * N + col]       = w0;
            *(float2*)&C[(size_t)(r0 + 8) * N + col] = w1;
        }
    }
}

// ---------------------------------------------------------------------------
// RoPE in place on t: [B*S, nheads, 128].
// ---------------------------------------------------------------------------
__global__ void rope_kernel(float* __restrict__ t, int nheads)
{
    const int idx = blockIdx.x * blockDim.x + threadIdx.x;
    const int j = idx & 63;
    const int rest = idx >> 6;
    const int head = rest % nheads;
    const int tok = rest / nheads;
    const int s = tok & (S_ - 1);

    const float expo = (float)(2 * j) / 128.0f;
    const float inv = 1.0f / powf(1.0e6f, expo);
    const float ang = (float)s * inv;
    float sn, cs;
    sincosf(ang, &sn, &cs);

    const size_t base = ((size_t)tok * nheads + head) * HD_;
    const float x1 = t[base + j];
    const float x2 = t[base + j + 64];
    t[base + j]      = x1 * cs - x2 * sn;
    t[base + j + 64] = x2 * cs + x1 * sn;
}

// ---------------------------------------------------------------------------
// Flash attention, fp32, causal, GQA. 64x64 tiles, 256 threads. (round-1)
// ---------------------------------------------------------------------------
#define FBM 64
#define FBN 64
#define TSTR 132
#define PSTR 68

__global__ __launch_bounds__(256) void flash_attn()
{
    extern __shared__ float sm[];
    float* Qs   = sm;
    float* Ks   = Qs + 64 * TSTR;
    float* Vs   = Ks + 64 * TSTR;
    float* Ps   = Vs + 64 * TSTR;
    float* mrow = Ps + 64 * PSTR;
    float* lrow = mrow + 64;
    float* arow = lrow + 64;

    const int qt = blockIdx.x;
    const int h  = blockIdx.y;
    const int b  = blockIdx.z;
    const int kvh = h / GROUPS_;
    const int tid = threadIdx.x;
    const int qbase = qt * FBM;

    const float* qptr = g_q + (((size_t)b * S_ + qbase) * NH_ + h) * HD_;
    #pragma unroll
    for (int it = 0; it < 8; it++) {
        int idx = tid + it * 256;
        int tok = idx >> 5;
        int hd  = (idx & 31) << 2;
        *(float4*)(Qs + tok * TSTR + hd) =
            *(const float4*)(qptr + (size_t)tok * NH_ * HD_ + hd);
    }
    if (tid < 64) { mrow[tid] = -1e30f; lrow[tid] = 0.0f; }

    const int ty = tid >> 4;
    const int tx = tid & 15;
    const int r0 = ty * 4;

    float oacc[4][8];
    #pragma unroll
    for (int i = 0; i < 4; i++)
        #pragma unroll
        for (int j = 0; j < 8; j++) oacc[i][j] = 0.0f;

    const float scale = 0.08838834764831845f;

    const float* kbp = g_k + ((size_t)b * S_ * NKV_ + kvh) * HD_;
    const float* vbp = g_v + ((size_t)b * S_ * NKV_ + kvh) * HD_;

    for (int jt = 0; jt <= qt; jt++) {
        __syncthreads();
        const float* kp = kbp + (size_t)(jt * FBN) * NKV_ * HD_;
        const float* vp = vbp + (size_t)(jt * FBN) * NKV_ * HD_;
        #pragma unroll
        for (int it = 0; it < 8; it++) {
            int idx = tid + it * 256;
            int tok = idx >> 5;
            int hd  = (idx & 31) << 2;
            *(float4*)(Ks + tok * TSTR + hd) =
                *(const float4*)(kp + (size_t)tok * NKV_ * HD_ + hd);
            *(float4*)(Vs + tok * TSTR + hd) =
                *(const float4*)(vp + (size_t)tok * NKV_ * HD_ + hd);
        }
        __syncthreads();

        float sacc[4][4];
        #pragma unroll
        for (int i = 0; i < 4; i++)
            #pragma unroll
            for (int j = 0; j < 4; j++) sacc[i][j] = 0.0f;

        #pragma unroll 4
        for (int kk = 0; kk < HD_; kk += 4) {
            float4 qr[4], kr[4];
            #pragma unroll
            for (int i = 0; i < 4; i++)
                qr[i] = *(const float4*)(Qs + (r0 + i) * TSTR + kk);
            #pragma unroll
            for (int j = 0; j < 4; j++)
                kr[j] = *(const float4*)(Ks + (tx + 16 * j) * TSTR + kk);
            #pragma unroll
            for (int i = 0; i < 4; i++)
                #pragma unroll
                for (int j = 0; j < 4; j++)
                    sacc[i][j] += qr[i].x * kr[j].x + qr[i].y * kr[j].y +
                                  qr[i].z * kr[j].z + qr[i].w * kr[j].w;
        }

        const bool diag = (jt == qt);
        #pragma unroll
        for (int i = 0; i < 4; i++) {
            const int rr = r0 + i;
            #pragma unroll
            for (int j = 0; j < 4; j++) {
                const int cc = tx + 16 * j;
                float sv = sacc[i][j] * scale;
                if (diag && cc > rr) sv = -1e30f;
                Ps[rr * PSTR + cc] = sv;
            }
        }
        __syncthreads();

        {
            const int row = tid >> 2;
            const int part = tid & 3;
            const int c0 = part * 16;
            float mx = -1e30f;
            #pragma unroll
            for (int c = 0; c < 16; c++)
                mx = fmaxf(mx, Ps[row * PSTR + c0 + c]);
            mx = fmaxf(mx, __shfl_xor_sync(0xffffffffu, mx, 1));
            mx = fmaxf(mx, __shfl_xor_sync(0xffffffffu, mx, 2));
            const float m_old = mrow[row];
            const float m_new = fmaxf(m_old, mx);
            float ssum = 0.0f;
            #pragma unroll
            for (int c = 0; c < 16; c++) {
                float p = __expf(Ps[row * PSTR + c0 + c] - m_new);
                Ps[row * PSTR + c0 + c] = p;
                ssum += p;
            }
            ssum += __shfl_xor_sync(0xffffffffu, ssum, 1);
            ssum += __shfl_xor_sync(0xffffffffu, ssum, 2);
            if (part == 0) {
                const float al = __expf(m_old - m_new);
                arow[row] = al;
                lrow[row] = lrow[row] * al + ssum;
                mrow[row] = m_new;
            }
        }
        __syncthreads();

        float al[4];
        #pragma unroll
        for (int i = 0; i < 4; i++) al[i] = arow[r0 + i];
        #pragma unroll
        for (int i = 0; i < 4; i++)
            #pragma unroll
            for (int j = 0; j < 8; j++) oacc[i][j] *= al[i];

        #pragma unroll 4
        for (int kk = 0; kk < FBN; kk++) {
            float pv[4];
            #pragma unroll
            for (int i = 0; i < 4; i++) pv[i] = Ps[(r0 + i) * PSTR + kk];
            float4 v0 = *(const float4*)(Vs + kk * TSTR + 4 * tx);
            float4 v1 = *(const float4*)(Vs + kk * TSTR + 64 + 4 * tx);
            #pragma unroll
            for (int i = 0; i < 4; i++) {
                oacc[i][0] += pv[i] * v0.x;  oacc[i][1] += pv[i] * v0.y;
                oacc[i][2] += pv[i] * v0.z;  oacc[i][3] += pv[i] * v0.w;
                oacc[i][4] += pv[i] * v1.x;  oacc[i][5] += pv[i] * v1.y;
                oacc[i][6] += pv[i] * v1.z;  oacc[i][7] += pv[i] * v1.w;
            }
        }
    }

    float* optr = g_ctx + (((size_t)b * S_ + qbase) * NH_ + h) * HD_;
    #pragma unroll
    for (int i = 0; i < 4; i++) {
        const float linv = 1.0f / lrow[r0 + i];
        const size_t off = (size_t)(r0 + i) * NH_ * HD_;
        float4 w0 = make_float4(oacc[i][0]*linv, oacc[i][1]*linv,
                                oacc[i][2]*linv, oacc[i][3]*linv);
        float4 w1 = make_float4(oacc[i][4]*linv, oacc[i][5]*linv,
                                oacc[i][6]*linv, oacc[i][7]*linv);
        *(float4*)(optr + off + 4 * tx) = w0;
        *(float4*)(optr + off + 64 + 4 * tx) = w1;
    }
}

// ---------------------------------------------------------------------------
extern "C" void kernel_launch(void* const* d_in, const int* in_sizes, int n_in,
                              void* d_out, int out_size)
{
    (void)in_sizes; (void)n_in; (void)out_size;
    const float* x    = (const float*)d_in[0];
    const float* wq_w = (const float*)d_in[1];
    const float* wq_b = (const float*)d_in[2];
    const float* wk_w = (const float*)d_in[3];
    const float* wk_b = (const float*)d_in[4];
    const float* wv_w = (const float*)d_in[5];
    const float* wv_b = (const float*)d_in[6];
    const float* wo_w = (const float*)d_in[7];
    float* out = (float*)d_out;

    float *pq, *pk, *pv, *pctx;
    cudaGetSymbolAddress((void**)&pq,   g_q);
    cudaGetSymbolAddress((void**)&pk,   g_k);
    cudaGetSymbolAddress((void**)&pv,   g_v);
    cudaGetSymbolAddress((void**)&pctx, g_ctx);

    __nv_bfloat16 *xh, *xl, *wqh, *wql, *wkh, *wkl, *wvh, *wvl, *woh, *wol, *ch, *cl;
    cudaGetSymbolAddress((void**)&xh,  g_xh);  cudaGetSymbolAddress((void**)&xl,  g_xl);
    cudaGetSymbolAddress((void**)&wqh, g_wqh); cudaGetSymbolAddress((void**)&wql, g_wql);
    cudaGetSymbolAddress((void**)&wkh, g_wkh); cudaGetSymbolAddress((void**)&wkl, g_wkl);
    cudaGetSymbolAddress((void**)&wvh, g_wvh); cudaGetSymbolAddress((void**)&wvl, g_wvl);
    cudaGetSymbolAddress((void**)&woh, g_woh); cudaGetSymbolAddress((void**)&wol, g_wol);
    cudaGetSymbolAddress((void**)&ch,  g_ch);  cudaGetSymbolAddress((void**)&cl,  g_cl);

    const size_t FL_SMEM = (size_t)(3 * 64 * TSTR + 64 * PSTR + 3 * 64) * sizeof(float);
    cudaFuncSetAttribute(flash_attn, cudaFuncAttributeMaxDynamicSharedMemorySize,
                         (int)FL_SMEM);
    cudaFuncSetAttribute(gemm_bf16x3, cudaFuncAttributeMaxDynamicSharedMemorySize,
                         SMEM_GEMM);

    // hi/lo splits of activations and weights
    split_bf16<<<(MTOK * D_ / 4) / 256, 256>>>(x,    xh,  xl,  MTOK * D_);
    split_bf16<<<(D_ * D_ / 4)   / 256, 256>>>(wq_w, wqh, wql, D_ * D_);
    split_bf16<<<(KVD * D_ / 4)  / 256, 256>>>(wk_w, wkh, wkl, KVD * D_);
    split_bf16<<<(KVD * D_ / 4)  / 256, 256>>>(wv_w, wvh, wvl, KVD * D_);
    split_bf16<<<(D_ * D_ / 4)   / 256, 256>>>(wo_w, woh, wol, D_ * D_);

    // QKV projections (tensor-core bf16x3)
    gemm_bf16x3<<<dim3(D_  / 128, MTOK / 128), 256, SMEM_GEMM>>>(
        xh, xl, wqh, wql, wq_b, pq, MTOK, D_,  D_);
    gemm_bf16x3<<<dim3(KVD / 128, MTOK / 128), 256, SMEM_GEMM>>>(
        xh, xl, wkh, wkl, wk_b, pk, MTOK, KVD, D_);
    gemm_bf16x3<<<dim3(KVD / 128, MTOK / 128), 256, SMEM_GEMM>>>(
        xh, xl, wvh, wvl, wv_b, pv, MTOK, KVD, D_);

    // RoPE on q and k
    rope_kernel<<<(MTOK * NH_  * 64) / 256, 256>>>(pq, NH_);
    rope_kernel<<<(MTOK * NKV_ * 64) / 256, 256>>>(pk, NKV_);

    // causal GQA flash attention -> g_ctx
    flash_attn<<<dim3(S_ / FBM, NH_, B_), 256, FL_SMEM>>>();

    // split ctx, then output projection
    split_bf16<<<(MTOK * D_ / 4) / 256, 256>>>(pctx, ch, cl, MTOK * D_);
    gemm_bf16x3<<<dim3(D_ / 128, MTOK / 128), 256, SMEM_GEMM>>>(
        ch, cl, woh, wol, nullptr, out, MTOK, D_, D_);
}

// round 4
// speedup vs baseline: 2.7513x; 1.6684x over previous
#include <cuda_runtime.h>
#include <cuda_bf16.h>
#include <math.h>
#include <cstdint>

#define B_ 4
#define S_ 2048
#define D_ 2048
#define NH_ 16
#define NKV_ 4
#define HD_ 128
#define GROUPS_ 4
#define MTOK (B_*S_)      /* 8192 */
#define KVD (NKV_*HD_)    /* 512  */

// fp32 scratch
__device__ float g_q[(size_t)MTOK * D_];
__device__ float g_k[(size_t)MTOK * KVD];
__device__ float g_v[(size_t)MTOK * KVD];
__device__ float g_ctx[(size_t)MTOK * D_];

// bf16 hi/lo split buffers (GEMM operands)
__device__ __nv_bfloat16 g_xh[(size_t)MTOK * D_];
__device__ __nv_bfloat16 g_xl[(size_t)MTOK * D_];
__device__ __nv_bfloat16 g_wqh[(size_t)D_ * D_];
__device__ __nv_bfloat16 g_wql[(size_t)D_ * D_];
__device__ __nv_bfloat16 g_wkh[(size_t)KVD * D_];
__device__ __nv_bfloat16 g_wkl[(size_t)KVD * D_];
__device__ __nv_bfloat16 g_wvh[(size_t)KVD * D_];
__device__ __nv_bfloat16 g_wvl[(size_t)KVD * D_];
__device__ __nv_bfloat16 g_woh[(size_t)D_ * D_];
__device__ __nv_bfloat16 g_wol[(size_t)D_ * D_];
__device__ __nv_bfloat16 g_ch[(size_t)MTOK * D_];
__device__ __nv_bfloat16 g_cl[(size_t)MTOK * D_];

// bf16 hi/lo attention operands (rope applied; q pre-scaled)
__device__ __nv_bfloat16 g_qh[(size_t)MTOK * D_];
__device__ __nv_bfloat16 g_ql[(size_t)MTOK * D_];
__device__ __nv_bfloat16 g_kh[(size_t)MTOK * KVD];
__device__ __nv_bfloat16 g_kl[(size_t)MTOK * KVD];
__device__ __nv_bfloat16 g_vh[(size_t)MTOK * KVD];
__device__ __nv_bfloat16 g_vl[(size_t)MTOK * KVD];

// ============================================================================
// helpers (portable PTX only: mma.sync / cp.async / ldmatrix, sm_80)
// ============================================================================
__device__ __forceinline__ uint32_t smem_u32(const void* p) {
    uint32_t a;
    asm("{ .reg .u64 t; cvta.to.shared.u64 t, %1; cvt.u32.u64 %0, t; }"
        : "=r"(a) : "l"(p));
    return a;
}
__device__ __forceinline__ uint32_t lds32(uint32_t a) {
    uint32_t v;
    asm volatile("ld.shared.b32 %0, [%1];" : "=r"(v) : "r"(a));
    return v;
}
__device__ __forceinline__ void cp16(uint32_t dst, const void* src) {
    asm volatile("cp.async.cg.shared.global [%0], [%1], 16;"
                 :: "r"(dst), "l"(src) : "memory");
}
__device__ __forceinline__ void mma_bf16(float* c,
    uint32_t a0, uint32_t a1, uint32_t a2, uint32_t a3,
    uint32_t b0, uint32_t b1)
{
    asm volatile(
        "mma.sync.aligned.m16n8k16.row.col.f32.bf16.bf16.f32 "
        "{%0,%1,%2,%3}, {%4,%5,%6,%7}, {%8,%9}, {%0,%1,%2,%3};"
        : "+f"(c[0]), "+f"(c[1]), "+f"(c[2]), "+f"(c[3])
        : "r"(a0), "r"(a1), "r"(a2), "r"(a3), "r"(b0), "r"(b1));
}
__device__ __forceinline__ void ldmx4t(uint32_t& d0, uint32_t& d1,
                                       uint32_t& d2, uint32_t& d3, uint32_t a)
{
    asm volatile(
        "ldmatrix.sync.aligned.m8n8.x4.trans.shared.b16 {%0,%1,%2,%3}, [%4];"
        : "=r"(d0), "=r"(d1), "=r"(d2), "=r"(d3) : "r"(a));
}

// ============================================================================
// split: fp32 -> hi bf16 + lo bf16
// ============================================================================
__global__ void split_bf16(const float* __restrict__ in,
                           __nv_bfloat16* __restrict__ hi,
                           __nv_bfloat16* __restrict__ lo, int n)
{
    const int i = (blockIdx.x * blockDim.x + threadIdx.x) * 4;
    if (i >= n) return;
    float4 v = *(const float4*)(in + i);
    __nv_bfloat16 h0 = __float2bfloat16(v.x);
    __nv_bfloat16 h1 = __float2bfloat16(v.y);
    __nv_bfloat16 h2 = __float2bfloat16(v.z);
    __nv_bfloat16 h3 = __float2bfloat16(v.w);
    __nv_bfloat16 l0 = __float2bfloat16(v.x - __bfloat162float(h0));
    __nv_bfloat16 l1 = __float2bfloat16(v.y - __bfloat162float(h1));
    __nv_bfloat16 l2 = __float2bfloat16(v.z - __bfloat162float(h2));
    __nv_bfloat16 l3 = __float2bfloat16(v.w - __bfloat162float(h3));
    __nv_bfloat162* H = (__nv_bfloat162*)(hi + i);
    __nv_bfloat162* L = (__nv_bfloat162*)(lo + i);
    H[0] = __halves2bfloat162(h0, h1);
    H[1] = __halves2bfloat162(h2, h3);
    L[0] = __halves2bfloat162(l0, l1);
    L[1] = __halves2bfloat162(l2, l3);
}

// ============================================================================
// fused RoPE + hi/lo split (+ optional scale): fp32 [tok][nh][128] -> bf16 x2
// thread handles cols (2j, 2j+1) and (64+2j, 65+2j)
// ============================================================================
__global__ void rope_split(const float* __restrict__ t,
                           __nv_bfloat16* __restrict__ hi,
                           __nv_bfloat16* __restrict__ lo,
                           int nheads, float scale)
{
    const int idx = blockIdx.x * blockDim.x + threadIdx.x;
    const int j = idx & 31;
    const int rest = idx >> 5;
    const int head = rest % nheads;
    const int tok = rest / nheads;
    const int s = tok & (S_ - 1);
    const size_t base = ((size_t)tok * nheads + head) * HD_;

    float y1[2], y2[2];
    #pragma unroll
    for (int u = 0; u < 2; u++) {
        const int c = 2 * j + u;
        const float expo = (float)(2 * c) / 128.0f;
        const float inv = 1.0f / powf(1.0e6f, expo);
        float sn, cs;
        sincosf((float)s * inv, &sn, &cs);
        const float x1 = t[base + c];
        const float x2 = t[base + c + 64];
        y1[u] = (x1 * cs - x2 * sn) * scale;
        y2[u] = (x2 * cs + x1 * sn) * scale;
    }
    __nv_bfloat162 h1 = __floats2bfloat162_rn(y1[0], y1[1]);
    float2 f1 = __bfloat1622float2(h1);
    __nv_bfloat162 l1v = __floats2bfloat162_rn(y1[0] - f1.x, y1[1] - f1.y);
    __nv_bfloat162 h2 = __floats2bfloat162_rn(y2[0], y2[1]);
    float2 f2 = __bfloat1622float2(h2);
    __nv_bfloat162 l2v = __floats2bfloat162_rn(y2[0] - f2.x, y2[1] - f2.y);
    *(__nv_bfloat162*)(hi + base + 2 * j) = h1;
    *(__nv_bfloat162*)(lo + base + 2 * j) = l1v;
    *(__nv_bfloat162*)(hi + base + 64 + 2 * j) = h2;
    *(__nv_bfloat162*)(lo + base + 64 + 2 * j) = l2v;
}

// ============================================================================
// bf16x3 GEMM (round-3, unchanged): C = A @ Bw^T (+bias), fp32 out.
// ============================================================================
#define RSTR 80
#define MATB (128 * RSTR)
#define STG  (4 * MATB)
#define SMEM_GEMM (2 * STG)

__global__ __launch_bounds__(256) void gemm_bf16x3(
    const __nv_bfloat16* __restrict__ Ah, const __nv_bfloat16* __restrict__ Al,
    const __nv_bfloat16* __restrict__ Bh, const __nv_bfloat16* __restrict__ Bl,
    const float* __restrict__ bias, float* __restrict__ C,
    int M, int N, int K)
{
    extern __shared__ char smc[];
    const uint32_t sb = smem_u32(smc);
    const int tid = threadIdx.x;
    const int wid = tid >> 5, lane = tid & 31;
    const int bm = blockIdx.y * 128, bn = blockIdx.x * 128;
    const int wm = wid & 1, wn = wid >> 1;
    const int g = lane >> 2, tg = lane & 3;

    float acc[4][4][4];
    #pragma unroll
    for (int i = 0; i < 4; i++)
        #pragma unroll
        for (int j = 0; j < 4; j++)
            #pragma unroll
            for (int r = 0; r < 4; r++) acc[i][j][r] = 0.0f;

    const int T = K / 32;

    auto issue = [&](int s, int k0) {
        const uint32_t sbase = sb + s * STG;
        #pragma unroll
        for (int i = 0; i < 2; i++) {
            const int idx = tid + i * 256;
            const int row = idx >> 2, c8 = idx & 3;
            const size_t goA = (size_t)(bm + row) * K + k0 + c8 * 8;
            const size_t goB = (size_t)(bn + row) * K + k0 + c8 * 8;
            const uint32_t so = (uint32_t)(row * RSTR + c8 * 16);
            cp16(sbase + so,            Ah + goA);
            cp16(sbase + MATB + so,     Al + goA);
            cp16(sbase + 2 * MATB + so, Bh + goB);
            cp16(sbase + 3 * MATB + so, Bl + goB);
        }
        asm volatile("cp.async.commit_group;" ::: "memory");
    };

    issue(0, 0);

    for (int t = 0; t < T; t++) {
        if (t + 1 < T) {
            issue((t + 1) & 1, (t + 1) * 32);
            asm volatile("cp.async.wait_group 1;" ::: "memory");
        } else {
            asm volatile("cp.async.wait_group 0;" ::: "memory");
        }
        __syncthreads();

        const uint32_t stb = sb + (t & 1) * STG;
        const uint32_t aB = stb + (uint32_t)((wm * 64 + g) * RSTR + tg * 4);
        const uint32_t bB = stb + 2 * MATB + (uint32_t)((wn * 32 + g) * RSTR + tg * 4);

        #pragma unroll
        for (int ks = 0; ks < 2; ks++) {
            const uint32_t ko = ks * 32;
            uint32_t bh[4][2], bl[4][2];
            #pragma unroll
            for (int nt = 0; nt < 4; nt++) {
                const uint32_t a = bB + nt * 8 * RSTR + ko;
                bh[nt][0] = lds32(a);
                bh[nt][1] = lds32(a + 16);
                bl[nt][0] = lds32(a + MATB);
                bl[nt][1] = lds32(a + MATB + 16);
            }
            #pragma unroll
            for (int mt = 0; mt < 4; mt++) {
                const uint32_t a = aB + mt * 16 * RSTR + ko;
                const uint32_t ah0 = lds32(a);
                const uint32_t ah1 = lds32(a + 8 * RSTR);
                const uint32_t ah2 = lds32(a + 16);
                const uint32_t ah3 = lds32(a + 8 * RSTR + 16);
                const uint32_t al0 = lds32(a + MATB);
                const uint32_t al1 = lds32(a + MATB + 8 * RSTR);
                const uint32_t al2 = lds32(a + MATB + 16);
                const uint32_t al3 = lds32(a + MATB + 8 * RSTR + 16);
                #pragma unroll
                for (int nt = 0; nt < 4; nt++) {
                    mma_bf16(acc[mt][nt], ah0, ah1, ah2, ah3, bh[nt][0], bh[nt][1]);
                    mma_bf16(acc[mt][nt], ah0, ah1, ah2, ah3, bl[nt][0], bl[nt][1]);
                    mma_bf16(acc[mt][nt], al0, al1, al2, al3, bh[nt][0], bh[nt][1]);
                }
            }
        }
        __syncthreads();
    }

    #pragma unroll
    for (int mt = 0; mt < 4; mt++) {
        const int r0 = bm + wm * 64 + mt * 16 + g;
        #pragma unroll
        for (int nt = 0; nt < 4; nt++) {
            const int col = bn + wn * 32 + nt * 8 + tg * 2;
            float b0 = 0.f, b1 = 0.f;
            if (bias) { b0 = bias[col]; b1 = bias[col + 1]; }
            float2 w0 = make_float2(acc[mt][nt][0] + b0, acc[mt][nt][1] + b1);
            float2 w1 = make_float2(acc[mt][nt][2] + b0, acc[mt][nt][3] + b1);
            *(float2*)&C[(size_t)r0 * N + col]       = w0;
            *(float2*)&C[(size_t)(r0 + 8) * N + col] = w1;
        }
    }
}

// ============================================================================
// Tensor-core flash attention (bf16x3), causal GQA.
// CTA = 64 q-rows, 4 warps (16 rows each), 64 kv per iter.
// smem tiles 64x128 bf16, row stride 136 elems (272 B; 68 words => 4g+tg banks)
// ============================================================================
#define FSTRB 272                 /* bytes per smem row */
#define FTILE_B (64 * FSTRB)      /* 17408 bytes per tile */
#define FSMEM (6 * FTILE_B)       /* qh ql kh kl vh vl = 104448 */

__global__ __launch_bounds__(128) void flash_mma()
{
    extern __shared__ char smf[];
    const uint32_t sb = smem_u32(smf);
    const uint32_t QH = 0,           QL = FTILE_B,
                   KH = 2 * FTILE_B, VH = 4 * FTILE_B;

    const int qt = blockIdx.x, h = blockIdx.y, b = blockIdx.z;
    const int kvh = h >> 2;
    const int tid = threadIdx.x;
    const int w = tid >> 5, lane = tid & 31;
    const int g = lane >> 2, tg = lane & 3;

    // ---- Q tile (loop-invariant) via cp.async
    {
        const size_t qoff = (((size_t)(b * S_ + qt * 64)) * NH_ + h) * HD_;
        const __nv_bfloat16* qhp = g_qh + qoff;
        const __nv_bfloat16* qlp = g_ql + qoff;
        #pragma unroll
        for (int i = 0; i < 8; i++) {
            const int c = tid + i * 128;
            const int row = c >> 4, o16 = c & 15;
            const uint32_t so = (uint32_t)(row * FSTRB + o16 * 16);
            const size_t go = (size_t)row * (NH_ * HD_) + o16 * 8;
            cp16(sb + QH + so, qhp + go);
            cp16(sb + QL + so, qlp + go);
        }
        asm volatile("cp.async.commit_group;" ::: "memory");
    }

    float o[16][4];
    #pragma unroll
    for (int n = 0; n < 16; n++)
        #pragma unroll
        for (int c = 0; c < 4; c++) o[n][c] = 0.0f;
    float m0 = -1e30f, m1 = -1e30f, l0 = 0.0f, l1 = 0.0f;

    const size_t kvoff = ((size_t)b * S_ * NKV_ + kvh) * HD_;
    const __nv_bfloat16* khp = g_kh + kvoff;
    const __nv_bfloat16* klp = g_kl + kvoff;
    const __nv_bfloat16* vhp = g_vh + kvoff;
    const __nv_bfloat16* vlp = g_vl + kvoff;

    const int r0l = 16 * w + g;       // local q row (and +8)

    for (int jt = 0; jt <= qt; jt++) {
        __syncthreads();
        {
            const size_t tb = (size_t)(jt * 64) * KVD;
            #pragma unroll
            for (int i = 0; i < 8; i++) {
                const int c = tid + i * 128;
                const int row = c >> 4, o16 = c & 15;
                const uint32_t so = (uint32_t)(row * FSTRB + o16 * 16);
                const size_t go = tb + (size_t)row * KVD + o16 * 8;
                cp16(sb + KH + so,           khp + go);
                cp16(sb + KH + FTILE_B + so, klp + go);
                cp16(sb + VH + so,           vhp + go);
                cp16(sb + VH + FTILE_B + so, vlp + go);
            }
            asm volatile("cp.async.commit_group;" ::: "memory");
            asm volatile("cp.async.wait_group 0;" ::: "memory");
        }
        __syncthreads();

        // ---- scores: S = Q @ K^T (3-term bf16x3)
        float sacc[8][4];
        #pragma unroll
        for (int n = 0; n < 8; n++)
            #pragma unroll
            for (int c = 0; c < 4; c++) sacc[n][c] = 0.0f;

        const uint32_t qrow = sb + QH + (uint32_t)((16 * w + g) * FSTRB + tg * 4);
        #pragma unroll
        for (int k0 = 0; k0 < 8; k0++) {
            const uint32_t qa = qrow + k0 * 32;
            const uint32_t ah0 = lds32(qa);
            const uint32_t ah1 = lds32(qa + 8 * FSTRB);
            const uint32_t ah2 = lds32(qa + 16);
            const uint32_t ah3 = lds32(qa + 8 * FSTRB + 16);
            const uint32_t al0 = lds32(qa + FTILE_B);
            const uint32_t al1 = lds32(qa + FTILE_B + 8 * FSTRB);
            const uint32_t al2 = lds32(qa + FTILE_B + 16);
            const uint32_t al3 = lds32(qa + FTILE_B + 8 * FSTRB + 16);
            #pragma unroll
            for (int n = 0; n < 8; n++) {
                const uint32_t kb = sb + KH +
                    (uint32_t)((n * 8 + g) * FSTRB + k0 * 32 + tg * 4);
                const uint32_t bh0 = lds32(kb);
                const uint32_t bh1 = lds32(kb + 16);
                const uint32_t bl0 = lds32(kb + FTILE_B);
                const uint32_t bl1 = lds32(kb + FTILE_B + 16);
                mma_bf16(sacc[n], ah0, ah1, ah2, ah3, bh0, bh1);
                mma_bf16(sacc[n], ah0, ah1, ah2, ah3, bl0, bl1);
                mma_bf16(sacc[n], al0, al1, al2, al3, bh0, bh1);
            }
        }

        // ---- causal mask on diagonal tile
        if (jt == qt) {
            #pragma unroll
            for (int n = 0; n < 8; n++) {
                const int col = n * 8 + 2 * tg;
                if (col     > r0l)     sacc[n][0] = -1e30f;
                if (col + 1 > r0l)     sacc[n][1] = -1e30f;
                if (col     > r0l + 8) sacc[n][2] = -1e30f;
                if (col + 1 > r0l + 8) sacc[n][3] = -1e30f;
            }
        }

        // ---- online softmax (rows g and g+8, reduce over tg lanes)
        float mx0 = -1e30f, mx1 = -1e30f;
        #pragma unroll
        for (int n = 0; n < 8; n++) {
            mx0 = fmaxf(mx0, fmaxf(sacc[n][0], sacc[n][1]));
            mx1 = fmaxf(mx1, fmaxf(sacc[n][2], sacc[n][3]));
        }
        mx0 = fmaxf(mx0, __shfl_xor_sync(0xffffffffu, mx0, 1));
        mx0 = fmaxf(mx0, __shfl_xor_sync(0xffffffffu, mx0, 2));
        mx1 = fmaxf(mx1, __shfl_xor_sync(0xffffffffu, mx1, 1));
        mx1 = fmaxf(mx1, __shfl_xor_sync(0xffffffffu, mx1, 2));
        const float nm0 = fmaxf(m0, mx0), nm1 = fmaxf(m1, mx1);
        const float a0 = __expf(m0 - nm0), a1 = __expf(m1 - nm1);
        m0 = nm0; m1 = nm1;

        float s0 = 0.0f, s1 = 0.0f;
        #pragma unroll
        for (int n = 0; n < 8; n++) {
            sacc[n][0] = __expf(sacc[n][0] - nm0);
            sacc[n][1] = __expf(sacc[n][1] - nm0);
            sacc[n][2] = __expf(sacc[n][2] - nm1);
            sacc[n][3] = __expf(sacc[n][3] - nm1);
            s0 += sacc[n][0] + sacc[n][1];
            s1 += sacc[n][2] + sacc[n][3];
        }
        s0 += __shfl_xor_sync(0xffffffffu, s0, 1);
        s0 += __shfl_xor_sync(0xffffffffu, s0, 2);
        s1 += __shfl_xor_sync(0xffffffffu, s1, 1);
        s1 += __shfl_xor_sync(0xffffffffu, s1, 2);
        l0 = l0 * a0 + s0;
        l1 = l1 * a1 + s1;

        #pragma unroll
        for (int n = 0; n < 16; n++) {
            o[n][0] *= a0; o[n][1] *= a0;
            o[n][2] *= a1; o[n][3] *= a1;
        }

        // ---- PV: O += P @ V (3-term), P packed to A-fragments in registers
        const int mset = lane >> 3, r = lane & 7;
        #pragma unroll
        for (int kt = 0; kt < 4; kt++) {
            __nv_bfloat162 t0 = __floats2bfloat162_rn(sacc[2*kt][0],   sacc[2*kt][1]);
            __nv_bfloat162 t1 = __floats2bfloat162_rn(sacc[2*kt][2],   sacc[2*kt][3]);
            __nv_bfloat162 t2 = __floats2bfloat162_rn(sacc[2*kt+1][0], sacc[2*kt+1][1]);
            __nv_bfloat162 t3 = __floats2bfloat162_rn(sacc[2*kt+1][2], sacc[2*kt+1][3]);
            float2 f0 = __bfloat1622float2(t0), f1 = __bfloat1622float2(t1);
            float2 f2 = __bfloat1622float2(t2), f3 = __bfloat1622float2(t3);
            __nv_bfloat162 u0 = __floats2bfloat162_rn(sacc[2*kt][0]-f0.x,   sacc[2*kt][1]-f0.y);
            __nv_bfloat162 u1 = __floats2bfloat162_rn(sacc[2*kt][2]-f1.x,   sacc[2*kt][3]-f1.y);
            __nv_bfloat162 u2 = __floats2bfloat162_rn(sacc[2*kt+1][0]-f2.x, sacc[2*kt+1][1]-f2.y);
            __nv_bfloat162 u3 = __floats2bfloat162_rn(sacc[2*kt+1][2]-f3.x, sacc[2*kt+1][3]-f3.y);
            const uint32_t ph0 = *(uint32_t*)&t0, ph1 = *(uint32_t*)&t1;
            const uint32_t ph2 = *(uint32_t*)&t2, ph3 = *(uint32_t*)&t3;
            const uint32_t pl0 = *(uint32_t*)&u0, pl1 = *(uint32_t*)&u1;
            const uint32_t pl2 = *(uint32_t*)&u2, pl3 = *(uint32_t*)&u3;

            const int kk = kt * 16 + (mset & 1) * 8 + r;
            #pragma unroll
            for (int np = 0; np < 8; np++) {
                const int nn = np * 16 + (mset >> 1) * 8;
                const uint32_t va = sb + VH + (uint32_t)(kk * FSTRB + nn * 2);
                uint32_t v0, v1, v2, v3, w0, w1, w2, w3;
                ldmx4t(v0, v1, v2, v3, va);
                ldmx4t(w0, w1, w2, w3, va + FTILE_B);
                mma_bf16(o[2*np],   ph0, ph1, ph2, ph3, v0, v1);
                mma_bf16(o[2*np],   ph0, ph1, ph2, ph3, w0, w1);
                mma_bf16(o[2*np],   pl0, pl1, pl2, pl3, v0, v1);
                mma_bf16(o[2*np+1], ph0, ph1, ph2, ph3, v2, v3);
                mma_bf16(o[2*np+1], ph0, ph1, ph2, ph3, w2, w3);
                mma_bf16(o[2*np+1], pl0, pl1, pl2, pl3, v2, v3);
            }
        }
    }

    // ---- epilogue: normalize, write fp32 ctx [tok][h][hd]
    const float il0 = 1.0f / l0, il1 = 1.0f / l1;
    float* op0 = g_ctx + (((size_t)(b * S_ + qt * 64 + 16 * w + g)) * NH_ + h) * HD_;
    float* op1 = op0 + (size_t)8 * NH_ * HD_;
    #pragma unroll
    for (int n = 0; n < 16; n++) {
        const int cc = n * 8 + tg * 2;
        *(float2*)&op0[cc] = make_float2(o[n][0] * il0, o[n][1] * il0);
        *(float2*)&op1[cc] = make_float2(o[n][2] * il1, o[n][3] * il1);
    }
}

// ---------------------------------------------------------------------------
extern "C" void kernel_launch(void* const* d_in, const int* in_sizes, int n_in,
                              void* d_out, int out_size)
{
    (void)in_sizes; (void)n_in; (void)out_size;
    const float* x    = (const float*)d_in[0];
    const float* wq_w = (const float*)d_in[1];
    const float* wq_b = (const float*)d_in[2];
    const float* wk_w = (const float*)d_in[3];
    const float* wk_b = (const float*)d_in[4];
    const float* wv_w = (const float*)d_in[5];
    const float* wv_b = (const float*)d_in[6];
    const float* wo_w = (const float*)d_in[7];
    float* out = (float*)d_out;

    float *pq, *pk, *pv, *pctx;
    cudaGetSymbolAddress((void**)&pq,   g_q);
    cudaGetSymbolAddress((void**)&pk,   g_k);
    cudaGetSymbolAddress((void**)&pv,   g_v);
    cudaGetSymbolAddress((void**)&pctx, g_ctx);

    __nv_bfloat16 *xh, *xl, *wqh, *wql, *wkh, *wkl, *wvh, *wvl, *woh, *wol, *ch, *cl;
    __nv_bfloat16 *qh, *ql, *kh, *kl, *vh, *vl;
    cudaGetSymbolAddress((void**)&xh,  g_xh);  cudaGetSymbolAddress((void**)&xl,  g_xl);
    cudaGetSymbolAddress((void**)&wqh, g_wqh); cudaGetSymbolAddress((void**)&wql, g_wql);
    cudaGetSymbolAddress((void**)&wkh, g_wkh); cudaGetSymbolAddress((void**)&wkl, g_wkl);
    cudaGetSymbolAddress((void**)&wvh, g_wvh); cudaGetSymbolAddress((void**)&wvl, g_wvl);
    cudaGetSymbolAddress((void**)&woh, g_woh); cudaGetSymbolAddress((void**)&wol, g_wol);
    cudaGetSymbolAddress((void**)&ch,  g_ch);  cudaGetSymbolAddress((void**)&cl,  g_cl);
    cudaGetSymbolAddress((void**)&qh,  g_qh);  cudaGetSymbolAddress((void**)&ql,  g_ql);
    cudaGetSymbolAddress((void**)&kh,  g_kh);  cudaGetSymbolAddress((void**)&kl,  g_kl);
    cudaGetSymbolAddress((void**)&vh,  g_vh);  cudaGetSymbolAddress((void**)&vl,  g_vl);

    cudaFuncSetAttribute(gemm_bf16x3, cudaFuncAttributeMaxDynamicSharedMemorySize,
                         SMEM_GEMM);
    cudaFuncSetAttribute(flash_mma, cudaFuncAttributeMaxDynamicSharedMemorySize,
                         FSMEM);

    // hi/lo splits of activations and weights
    split_bf16<<<(MTOK * D_ / 4) / 256, 256>>>(x,    xh,  xl,  MTOK * D_);
    split_bf16<<<(D_ * D_ / 4)   / 256, 256>>>(wq_w, wqh, wql, D_ * D_);
    split_bf16<<<(KVD * D_ / 4)  / 256, 256>>>(wk_w, wkh, wkl, KVD * D_);
    split_bf16<<<(KVD * D_ / 4)  / 256, 256>>>(wv_w, wvh, wvl, KVD * D_);
    split_bf16<<<(D_ * D_ / 4)   / 256, 256>>>(wo_w, woh, wol, D_ * D_);

    // QKV projections (tensor-core bf16x3)
    gemm_bf16x3<<<dim3(D_  / 128, MTOK / 128), 256, SMEM_GEMM>>>(
        xh, xl, wqh, wql, wq_b, pq, MTOK, D_,  D_);
    gemm_bf16x3<<<dim3(KVD / 128, MTOK / 128), 256, SMEM_GEMM>>>(
        xh, xl, wkh, wkl, wk_b, pk, MTOK, KVD, D_);
    gemm_bf16x3<<<dim3(KVD / 128, MTOK / 128), 256, SMEM_GEMM>>>(
        xh, xl, wvh, wvl, wv_b, pv, MTOK, KVD, D_);

    // RoPE + split to bf16 hi/lo (q pre-scaled by 1/sqrt(HD)); v plain split
    rope_split<<<(MTOK * NH_  * 32) / 256, 256>>>(pq, qh, ql, NH_,
                                                  0.08838834764831845f);
    rope_split<<<(MTOK * NKV_ * 32) / 256, 256>>>(pk, kh, kl, NKV_, 1.0f);
    split_bf16<<<(MTOK * KVD / 4) / 256, 256>>>(pv, vh, vl, MTOK * KVD);

    // tensor-core causal GQA flash attention -> g_ctx (fp32)
    flash_mma<<<dim3(S_ / 64, NH_, B_), 128, FSMEM>>>();

    // split ctx, then output projection
    split_bf16<<<(MTOK * D_ / 4) / 256, 256>>>(pctx, ch, cl, MTOK * D_);
    gemm_bf16x3<<<dim3(D_ / 128, MTOK / 128), 256, SMEM_GEMM>>>(
        ch, cl, woh, wol, nullptr, out, MTOK, D_, D_);
}